// round 1
// baseline (speedup 1.0000x reference)
#include <cuda_runtime.h>

#define BSZ   4096
#define NNODE 16
#define OBSP  10
#define HID   128
#define NTH   128

// ---- packed f32x2 helpers (sm_100+ PTX; ptxas never auto-fuses these) ----
__device__ __forceinline__ unsigned long long pk2(float lo, float hi) {
    unsigned long long r;
    asm("mov.b64 %0, {%1, %2};" : "=l"(r) : "f"(lo), "f"(hi));
    return r;
}
__device__ __forceinline__ void upk2(unsigned long long v, float& lo, float& hi) {
    asm("mov.b64 {%0, %1}, %2;" : "=f"(lo), "=f"(hi) : "l"(v));
}
__device__ __forceinline__ void ffma2(unsigned long long& d,
                                      unsigned long long a, unsigned long long b) {
    asm("fma.rn.f32x2 %0, %1, %2, %0;" : "+l"(d) : "l"(a), "l"(b));
}

__global__ void __launch_bounds__(NTH)
gcn_fused(const float* __restrict__ obs, const float* __restrict__ act,
          const float* __restrict__ Q1W0, const float* __restrict__ Q1b0,
          const float* __restrict__ Q1W1, const float* __restrict__ Q1b1,
          const float* __restrict__ Q1W2, const float* __restrict__ Q1b2,
          const float* __restrict__ Q2W0, const float* __restrict__ Q2b0,
          const float* __restrict__ Q2W1, const float* __restrict__ Q2b1,
          const float* __restrict__ Q2W2, const float* __restrict__ Q2b2,
          float* __restrict__ out)
{
    // Shared: A (16x16 symmetric), transposed h0 tile Hs[k][i] stride 20 (16B-aligned
    // rows: 80B; 4-way STS conflicts only on the 16 stores/thread/layer — negligible).
    __shared__ __align__(16) float A[NNODE][NNODE];
    __shared__ __align__(16) float Hs[HID * 20];
    __shared__ float Xs[NNODE][OBSP];
    __shared__ float lx[NNODE], ly[NNODE], dinv[NNODE];
    __shared__ float red[4][NNODE];
    __shared__ float y2s[NNODE];

    const int g = blockIdx.x;
    const int t = threadIdx.x;
    const int warp = t >> 5, lane = t & 31;

    // ---- load features: x = [obs cols 2..9, action cols 0..1], loc = obs cols 0..1
    const float* ob = obs + (size_t)g * (NNODE * OBSP);
    for (int idx = t; idx < NNODE * OBSP; idx += NTH) {
        int n = idx / OBSP, k = idx - n * OBSP;
        float v = ob[idx];
        if (k == 0)      lx[n] = v;
        else if (k == 1) ly[n] = v;
        else             Xs[n][k - 2] = v;
    }
    if (t < NNODE * 2) {
        int n = t >> 1, k = t & 1;
        Xs[n][8 + k] = act[(size_t)g * (NNODE * 2) + t];
    }
    __syncthreads();

    // ---- adjacency: w_ij = exp(-||loc_i - loc_j||)  (256 entries, 2/thread)
    {
        int e = t * 2;
        #pragma unroll
        for (int r = 0; r < 2; r++, e++) {
            int i = e >> 4, j = e & 15;
            float dx = lx[i] - lx[j], dy = ly[i] - ly[j];
            A[i][j] = expf(-sqrtf(dx * dx + dy * dy));
        }
    }
    __syncthreads();
    if (t < NNODE) {
        float s = 0.f;
        #pragma unroll
        for (int j = 0; j < NNODE; j++) s += A[t][j];
        dinv[t] = rsqrtf(s);            // deg >= 1 always (self-loop w=1)
    }
    __syncthreads();
    {
        int e = t * 2;
        #pragma unroll
        for (int r = 0; r < 2; r++, e++) {
            int i = e >> 4, j = e & 15;
            A[i][j] *= dinv[i] * dinv[j];   // symmetric normalized adjacency
        }
    }
    __syncthreads();

    const float* W0a[2] = {Q1W0, Q2W0};
    const float* B0a[2] = {Q1b0, Q2b0};
    const float* W1a[2] = {Q1W1, Q2W1};
    const float* B1a[2] = {Q1b1, Q2b1};
    const float* W2a[2] = {Q1W2, Q2W2};
    const float* B2a[2] = {Q1b2, Q2b2};

    #pragma unroll
    for (int q = 0; q < 2; q++) {
        const float* W0 = W0a[q];
        const float* W1 = W1a[q];
        const float* W2 = W2a[q];

        // ---- layer 0: y0[i] = sum_k Xs[i][k] * W0[k][t]   (thread t = hidden col)
        float w0r[OBSP];
        #pragma unroll
        for (int k = 0; k < OBSP; k++) w0r[k] = __ldg(W0 + k * HID + t);
        float y[NNODE];
        #pragma unroll
        for (int i = 0; i < NNODE; i++) {
            float s = 0.f;
            #pragma unroll
            for (int k = 0; k < OBSP; k++) s = fmaf(Xs[i][k], w0r[k], s);
            y[i] = s;
        }
        // A-agg + bias + relu -> h0 stored transposed to Hs  (f32x2 over row pairs)
        {
            unsigned long long acc[8];
            #pragma unroll
            for (int p = 0; p < 8; p++) acc[p] = 0ull;
            #pragma unroll
            for (int j = 0; j < NNODE; j++) {
                unsigned long long yd = pk2(y[j], y[j]);
                const ulonglong2* Aj = reinterpret_cast<const ulonglong2*>(&A[j][0]);
                #pragma unroll
                for (int u = 0; u < 4; u++) {
                    ulonglong2 a2 = Aj[u];             // A[j][i] == A[i][j]
                    ffma2(acc[2 * u + 0], a2.x, yd);
                    ffma2(acc[2 * u + 1], a2.y, yd);
                }
            }
            float b0v = __ldg(B0a[q] + t);
            #pragma unroll
            for (int p = 0; p < 8; p++) {
                float lo, hi; upk2(acc[p], lo, hi);
                Hs[t * 20 + 2 * p + 0] = fmaxf(lo + b0v, 0.f);
                Hs[t * 20 + 2 * p + 1] = fmaxf(hi + b0v, 0.f);
            }
        }
        __syncthreads();

        // ---- layer 1 (dominant): y1[i] = sum_k h0[i][k] * W1[k][t]
        unsigned long long acc[8];
        #pragma unroll
        for (int p = 0; p < 8; p++) acc[p] = 0ull;
        const float* W1c = W1 + t;
        const ulonglong2* H2 = reinterpret_cast<const ulonglong2*>(Hs);
        #pragma unroll 8
        for (int k = 0; k < HID; k++) {
            float w = __ldg(W1c + k * HID);            // coalesced, L1-resident
            unsigned long long wd = pk2(w, w);
            const ulonglong2* row = H2 + k * 5;        // 80B rows, broadcast LDS.128
            ulonglong2 r0 = row[0], r1 = row[1], r2 = row[2], r3 = row[3];
            ffma2(acc[0], r0.x, wd); ffma2(acc[1], r0.y, wd);
            ffma2(acc[2], r1.x, wd); ffma2(acc[3], r1.y, wd);
            ffma2(acc[4], r2.x, wd); ffma2(acc[5], r2.y, wd);
            ffma2(acc[6], r3.x, wd); ffma2(acc[7], r3.y, wd);
        }
        float y1[NNODE];
        #pragma unroll
        for (int p = 0; p < 8; p++) upk2(acc[p], y1[2 * p], y1[2 * p + 1]);

        // A-agg + b1 + relu -> h1 stays in registers
        float h1[NNODE];
        {
            unsigned long long ag[8];
            #pragma unroll
            for (int p = 0; p < 8; p++) ag[p] = 0ull;
            #pragma unroll
            for (int j = 0; j < NNODE; j++) {
                unsigned long long yd = pk2(y1[j], y1[j]);
                const ulonglong2* Aj = reinterpret_cast<const ulonglong2*>(&A[j][0]);
                #pragma unroll
                for (int u = 0; u < 4; u++) {
                    ulonglong2 a2 = Aj[u];
                    ffma2(ag[2 * u + 0], a2.x, yd);
                    ffma2(ag[2 * u + 1], a2.y, yd);
                }
            }
            float b1v = __ldg(B1a[q] + t);
            #pragma unroll
            for (int p = 0; p < 8; p++) {
                float lo, hi; upk2(ag[p], lo, hi);
                h1[2 * p + 0] = fmaxf(lo + b1v, 0.f);
                h1[2 * p + 1] = fmaxf(hi + b1v, 0.f);
            }
        }

        // ---- layer 2: y2[i] = sum_t h1[i][t] * W2[t]  (cross-thread reduction)
        float w2 = __ldg(W2 + t);
        float part[NNODE];
        #pragma unroll
        for (int i = 0; i < NNODE; i++) part[i] = h1[i] * w2;
        #pragma unroll
        for (int off = 16; off > 0; off >>= 1) {
            #pragma unroll
            for (int i = 0; i < NNODE; i++)
                part[i] += __shfl_xor_sync(0xffffffffu, part[i], off);
        }
        __syncthreads();                 // Hs/red/y2s reads from prior phase complete
        if (lane == 0) {
            #pragma unroll
            for (int i = 0; i < NNODE; i++) red[warp][i] = part[i];
        }
        __syncthreads();
        if (t < NNODE)
            y2s[t] = red[0][t] + red[1][t] + red[2][t] + red[3][t];
        __syncthreads();
        if (t < NNODE) {
            float o = __ldg(B2a[q]);     // b2 scalar
            #pragma unroll
            for (int j = 0; j < NNODE; j++) o = fmaf(A[t][j], y2s[j], o);
            out[(size_t)q * BSZ * NNODE + (size_t)g * NNODE + t] = o;
        }
        __syncthreads();                 // before next head overwrites Hs/red/y2s
    }
}

extern "C" void kernel_launch(void* const* d_in, const int* in_sizes, int n_in,
                              void* d_out, int out_size)
{
    (void)in_sizes; (void)n_in; (void)out_size;
    gcn_fused<<<BSZ, NTH>>>(
        (const float*)d_in[0],  (const float*)d_in[1],
        (const float*)d_in[2],  (const float*)d_in[3],
        (const float*)d_in[4],  (const float*)d_in[5],
        (const float*)d_in[6],  (const float*)d_in[7],
        (const float*)d_in[8],  (const float*)d_in[9],
        (const float*)d_in[10], (const float*)d_in[11],
        (const float*)d_in[12], (const float*)d_in[13],
        (float*)d_out);
}

// round 2
// speedup vs baseline: 1.2885x; 1.2885x over previous
#include <cuda_runtime.h>

#define BSZ   4096
#define NNODE 16
#define OBSP  10
#define HID   128
#define GPB   4      // graphs per block (one warp each)
#define NTH   128

typedef unsigned long long ull;

// ---- packed f32x2 helpers (sm_103a; ptxas never auto-fuses these) ----
__device__ __forceinline__ ull pk2(float lo, float hi) {
    ull r; asm("mov.b64 %0, {%1, %2};" : "=l"(r) : "f"(lo), "f"(hi)); return r;
}
__device__ __forceinline__ void upk2(ull v, float& lo, float& hi) {
    asm("mov.b64 {%0, %1}, %2;" : "=f"(lo), "=f"(hi) : "l"(v));
}
__device__ __forceinline__ void ffma2(ull& d, ull a, ull b) {
    asm("fma.rn.f32x2 %0, %1, %2, %0;" : "+l"(d) : "l"(a), "l"(b));
}
__device__ __forceinline__ void add2(ull& d, ull a) {
    asm("add.rn.f32x2 %0, %0, %1;" : "+l"(d) : "l"(a));
}

struct __align__(16) GSh {
    float A[NNODE][NNODE];   // normalized adjacency (symmetric), rows 64B
    float Hs[HID][20];       // h0 transposed [col][row0..15], 80B stride (16B aligned)
    float Xt[OBSP][NNODE];   // input features transposed [featdim][node]
    float lx[NNODE], ly[NNODE], dinv[NNODE];
};

#define LOADROW8(dst, ptr) do { \
    const ulonglong2* _p = reinterpret_cast<const ulonglong2*>(ptr); \
    ulonglong2 _a = _p[0], _b = _p[1], _c = _p[2], _d = _p[3]; \
    dst[0]=_a.x; dst[1]=_a.y; dst[2]=_b.x; dst[3]=_b.y; \
    dst[4]=_c.x; dst[5]=_c.y; dst[6]=_d.x; dst[7]=_d.y; } while(0)

__global__ void __launch_bounds__(NTH)
gcn_fused2(const float* __restrict__ obs, const float* __restrict__ act,
           const float* __restrict__ Q1W0, const float* __restrict__ Q1b0,
           const float* __restrict__ Q1W1, const float* __restrict__ Q1b1,
           const float* __restrict__ Q1W2, const float* __restrict__ Q1b2,
           const float* __restrict__ Q2W0, const float* __restrict__ Q2b0,
           const float* __restrict__ Q2W1, const float* __restrict__ Q2b1,
           const float* __restrict__ Q2W2, const float* __restrict__ Q2b2,
           float* __restrict__ out)
{
    __shared__ GSh sh[GPB];
    const int warp = threadIdx.x >> 5;
    const int lane = threadIdx.x & 31;
    GSh& S = sh[warp];
    const int g = blockIdx.x * GPB + warp;   // one warp == one graph

    // ---- features: loc = obs cols 0,1; x = obs cols 2..9 ++ action cols 0,1
    {
        const float* ob = obs + (size_t)g * (NNODE * OBSP);
        #pragma unroll
        for (int r = 0; r < 5; r++) {
            int idx = lane + 32 * r;
            float v = ob[idx];
            int n = idx / OBSP, k = idx - n * OBSP;
            if (k == 0)      S.lx[n] = v;
            else if (k == 1) S.ly[n] = v;
            else             S.Xt[k - 2][n] = v;
        }
        float v = act[(size_t)g * (NNODE * 2) + lane];   // 32 vals == warp
        S.Xt[8 + (lane & 1)][lane >> 1] = v;
    }
    __syncwarp();

    // ---- adjacency w_ij = exp(-||loc_i - loc_j||); bitwise-symmetric
    #pragma unroll
    for (int r = 0; r < 8; r++) {
        int e = lane * 8 + r, i = e >> 4, j = e & 15;
        float dx = S.lx[i] - S.lx[j], dy = S.ly[i] - S.ly[j];
        S.A[i][j] = expf(-sqrtf(dx * dx + dy * dy));
    }
    __syncwarp();
    if (lane < NNODE) {
        float s = 0.f;
        #pragma unroll
        for (int j = 0; j < NNODE; j++) s += S.A[j][lane];  // column==row (symmetric), conflict-free
        S.dinv[lane] = rsqrtf(s);                           // deg >= 1 (self loop)
    }
    __syncwarp();
    #pragma unroll
    for (int r = 0; r < 8; r++) {
        int e = lane * 8 + r, i = e >> 4, j = e & 15;
        S.A[i][j] *= S.dinv[i] * S.dinv[j];
    }
    __syncwarp();

    const float* W0a[2] = {Q1W0, Q2W0};  const float* B0a[2] = {Q1b0, Q2b0};
    const float* W1a[2] = {Q1W1, Q2W1};  const float* B1a[2] = {Q1b1, Q2b1};
    const float* W2a[2] = {Q1W2, Q2W2};  const float* B2a[2] = {Q1b2, Q2b2};

    #pragma unroll
    for (int q = 0; q < 2; q++) {
        const float* W0 = W0a[q];
        const float* W1 = W1a[q];

        // acc[p*8+m] = y[rows 2m,2m+1][col lane+32p]
        ull acc[32];
        #pragma unroll
        for (int p = 0; p < 32; p++) acc[p] = 0ull;

        // ---- layer 0 GEMM: y0 = X @ W0   (k = 0..9)
        #pragma unroll
        for (int k = 0; k < OBSP; k++) {
            const float* Wk = W0 + k * HID + lane;
            float w0 = __ldg(Wk), w1 = __ldg(Wk + 32), w2 = __ldg(Wk + 64), w3 = __ldg(Wk + 96);
            ull row[8]; LOADROW8(row, S.Xt[k]);
            ull wd;
            wd = pk2(w0, w0);
            #pragma unroll
            for (int m = 0; m < 8; m++) ffma2(acc[m],      row[m], wd);
            wd = pk2(w1, w1);
            #pragma unroll
            for (int m = 0; m < 8; m++) ffma2(acc[8 + m],  row[m], wd);
            wd = pk2(w2, w2);
            #pragma unroll
            for (int m = 0; m < 8; m++) ffma2(acc[16 + m], row[m], wd);
            wd = pk2(w3, w3);
            #pragma unroll
            for (int m = 0; m < 8; m++) ffma2(acc[24 + m], row[m], wd);
        }

        // ---- agg0 = A @ y0, + b0, relu -> Hs (transposed). 2 cols per pass.
        #pragma unroll
        for (int pp = 0; pp < 2; pp++) {
            ull agg[16];
            #pragma unroll
            for (int m = 0; m < 16; m++) agg[m] = 0ull;
            #pragma unroll
            for (int j = 0; j < NNODE; j++) {
                ull ar[8]; LOADROW8(ar, S.A[j]);   // col j of A over rows (symmetric)
                {
                    float lo, hi; upk2(acc[(2 * pp) * 8 + (j >> 1)], lo, hi);
                    float yv = (j & 1) ? hi : lo;
                    ull yd = pk2(yv, yv);
                    #pragma unroll
                    for (int m = 0; m < 8; m++) ffma2(agg[m], ar[m], yd);
                }
                {
                    float lo, hi; upk2(acc[(2 * pp + 1) * 8 + (j >> 1)], lo, hi);
                    float yv = (j & 1) ? hi : lo;
                    ull yd = pk2(yv, yv);
                    #pragma unroll
                    for (int m = 0; m < 8; m++) ffma2(agg[8 + m], ar[m], yd);
                }
            }
            #pragma unroll
            for (int pc = 0; pc < 2; pc++) {
                int p = 2 * pp + pc;
                int c = lane + 32 * p;
                float b = __ldg(B0a[q] + c);
                float h[16];
                #pragma unroll
                for (int m = 0; m < 8; m++) {
                    float lo, hi; upk2(agg[pc * 8 + m], lo, hi);
                    h[2 * m]     = fmaxf(lo + b, 0.f);
                    h[2 * m + 1] = fmaxf(hi + b, 0.f);
                }
                float4* dst = reinterpret_cast<float4*>(&S.Hs[c][0]);
                dst[0] = make_float4(h[0],  h[1],  h[2],  h[3]);
                dst[1] = make_float4(h[4],  h[5],  h[6],  h[7]);
                dst[2] = make_float4(h[8],  h[9],  h[10], h[11]);
                dst[3] = make_float4(h[12], h[13], h[14], h[15]);
            }
        }
        __syncwarp();

        // ---- layer 1 GEMM (dominant): y1 = h0 @ W1  (k = 0..127)
        #pragma unroll
        for (int p = 0; p < 32; p++) acc[p] = 0ull;
        const float* W1c = W1 + lane;
        #pragma unroll 4
        for (int k = 0; k < HID; k++) {
            const float* Wk = W1c + k * HID;
            float w0 = __ldg(Wk), w1 = __ldg(Wk + 32), w2 = __ldg(Wk + 64), w3 = __ldg(Wk + 96);
            ull row[8]; LOADROW8(row, S.Hs[k]);    // broadcast, 80B stride
            ull wd;
            wd = pk2(w0, w0);
            #pragma unroll
            for (int m = 0; m < 8; m++) ffma2(acc[m],      row[m], wd);
            wd = pk2(w1, w1);
            #pragma unroll
            for (int m = 0; m < 8; m++) ffma2(acc[8 + m],  row[m], wd);
            wd = pk2(w2, w2);
            #pragma unroll
            for (int m = 0; m < 8; m++) ffma2(acc[16 + m], row[m], wd);
            wd = pk2(w3, w3);
            #pragma unroll
            for (int m = 0; m < 8; m++) ffma2(acc[24 + m], row[m], wd);
        }

        // ---- agg1 = A @ y1, + b1, relu -> h1; fuse layer-2 partial: part += h1 * W2[c]
        float w2c[4], b1c[4];
        #pragma unroll
        for (int p = 0; p < 4; p++) {
            w2c[p] = __ldg(W2a[q] + lane + 32 * p);
            b1c[p] = __ldg(B1a[q] + lane + 32 * p);
        }
        ull part[8];
        #pragma unroll
        for (int m = 0; m < 8; m++) part[m] = 0ull;

        #pragma unroll
        for (int pp = 0; pp < 2; pp++) {
            ull agg[16];
            #pragma unroll
            for (int m = 0; m < 16; m++) agg[m] = 0ull;
            #pragma unroll
            for (int j = 0; j < NNODE; j++) {
                ull ar[8]; LOADROW8(ar, S.A[j]);
                {
                    float lo, hi; upk2(acc[(2 * pp) * 8 + (j >> 1)], lo, hi);
                    float yv = (j & 1) ? hi : lo;
                    ull yd = pk2(yv, yv);
                    #pragma unroll
                    for (int m = 0; m < 8; m++) ffma2(agg[m], ar[m], yd);
                }
                {
                    float lo, hi; upk2(acc[(2 * pp + 1) * 8 + (j >> 1)], lo, hi);
                    float yv = (j & 1) ? hi : lo;
                    ull yd = pk2(yv, yv);
                    #pragma unroll
                    for (int m = 0; m < 8; m++) ffma2(agg[8 + m], ar[m], yd);
                }
            }
            #pragma unroll
            for (int pc = 0; pc < 2; pc++) {
                int p = 2 * pp + pc;
                float b = b1c[p];
                ull w2d = pk2(w2c[p], w2c[p]);
                #pragma unroll
                for (int m = 0; m < 8; m++) {
                    float lo, hi; upk2(agg[pc * 8 + m], lo, hi);
                    lo = fmaxf(lo + b, 0.f);
                    hi = fmaxf(hi + b, 0.f);
                    ffma2(part[m], pk2(lo, hi), w2d);
                }
            }
        }

        // ---- reduce part over the warp (sum over all 128 hidden cols)
        #pragma unroll
        for (int off = 16; off > 0; off >>= 1) {
            #pragma unroll
            for (int m = 0; m < 8; m++) {
                ull o = __shfl_xor_sync(0xffffffffu, part[m], off);
                add2(part[m], o);
            }
        }

        // ---- final agg: out[i] = b2 + sum_j A[i][j] * y2[j]
        if (lane < NNODE) {
            float y2[16];
            #pragma unroll
            for (int m = 0; m < 8; m++) upk2(part[m], y2[2 * m], y2[2 * m + 1]);
            float o = __ldg(B2a[q]);
            #pragma unroll
            for (int j = 0; j < NNODE; j++)
                o = fmaf(S.A[j][lane], y2[j], o);   // row j contiguous: conflict-free
            out[(size_t)q * BSZ * NNODE + (size_t)g * NNODE + lane] = o;
        }
        __syncwarp();   // before next head overwrites Hs
    }
}

extern "C" void kernel_launch(void* const* d_in, const int* in_sizes, int n_in,
                              void* d_out, int out_size)
{
    (void)in_sizes; (void)n_in; (void)out_size;
    gcn_fused2<<<BSZ / GPB, NTH>>>(
        (const float*)d_in[0],  (const float*)d_in[1],
        (const float*)d_in[2],  (const float*)d_in[3],
        (const float*)d_in[4],  (const float*)d_in[5],
        (const float*)d_in[6],  (const float*)d_in[7],
        (const float*)d_in[8],  (const float*)d_in[9],
        (const float*)d_in[10], (const float*)d_in[11],
        (const float*)d_in[12], (const float*)d_in[13],
        (float*)d_out);
}